// round 2
// baseline (speedup 1.0000x reference)
#include <cuda_runtime.h>

#define H_ 12
#define C_ 768
#define D_ 64
#define B_ 4
#define N_ 2048
#define M_ 8192   // B_*N_

// Scratch (allocation-free: __device__ globals)
__device__ float g_Q[B_ * H_ * N_ * D_];
__device__ float g_K[B_ * H_ * N_ * D_];
__device__ float g_V[B_ * H_ * N_ * D_];
__device__ float g_ctx[M_ * C_];

// ---------------------------------------------------------------------------
// 128x128x8 fp32 SGEMM, 256 threads, 8x8 microtile.
// MODE 0: Cout[row*N+col] = acc + bias[col]            (proj)
// MODE 1: scatter into g_Q (scaled by 0.125), g_K, g_V (qkv)
// ---------------------------------------------------------------------------
template <int MODE>
__global__ __launch_bounds__(256) void sgemm128(
    const float* __restrict__ A, const float* __restrict__ B,
    const float* __restrict__ bias, float* __restrict__ Cout,
    int K, int N)
{
    __shared__ float As[8][128];
    __shared__ float Bs[8][128];
    const int tid = threadIdx.x;
    const int m0 = blockIdx.y * 128;
    const int n0 = blockIdx.x * 128;
    const int tx = tid & 15;
    const int ty = tid >> 4;

    float acc[8][8];
#pragma unroll
    for (int i = 0; i < 8; i++)
#pragma unroll
        for (int j = 0; j < 8; j++) acc[i][j] = 0.f;

    const int aRow = tid >> 1;          // 0..127
    const int aCol = (tid & 1) * 4;     // 0 or 4
    const int bRow = tid >> 5;          // 0..7
    const int bCol = (tid & 31) * 4;    // 0..124
    const float* Ap = A + (size_t)(m0 + aRow) * K + aCol;
    const float* Bp = B + (size_t)bRow * N + n0 + bCol;

    for (int k0 = 0; k0 < K; k0 += 8) {
        float4 av = *(const float4*)(Ap + k0);
        float4 bv = *(const float4*)(Bp + (size_t)k0 * N);
        As[aCol + 0][aRow] = av.x;
        As[aCol + 1][aRow] = av.y;
        As[aCol + 2][aRow] = av.z;
        As[aCol + 3][aRow] = av.w;
        *(float4*)&Bs[bRow][bCol] = bv;
        __syncthreads();
#pragma unroll
        for (int kk = 0; kk < 8; kk++) {
            float ar[8], br[8];
            *(float4*)(ar)     = *(const float4*)&As[kk][ty * 8];
            *(float4*)(ar + 4) = *(const float4*)&As[kk][ty * 8 + 4];
            *(float4*)(br)     = *(const float4*)&Bs[kk][tx * 8];
            *(float4*)(br + 4) = *(const float4*)&Bs[kk][tx * 8 + 4];
#pragma unroll
            for (int i = 0; i < 8; i++)
#pragma unroll
                for (int j = 0; j < 8; j++)
                    acc[i][j] += ar[i] * br[j];
        }
        __syncthreads();
    }

    if (MODE == 0) {
#pragma unroll
        for (int i = 0; i < 8; i++) {
            int row = m0 + ty * 8 + i;
#pragma unroll
            for (int j = 0; j < 8; j += 4) {
                int col = n0 + tx * 8 + j;
                float4 v;
                v.x = acc[i][j + 0] + bias[col + 0];
                v.y = acc[i][j + 1] + bias[col + 1];
                v.z = acc[i][j + 2] + bias[col + 2];
                v.w = acc[i][j + 3] + bias[col + 3];
                *(float4*)(Cout + (size_t)row * N + col) = v;
            }
        }
    } else {
#pragma unroll
        for (int i = 0; i < 8; i++) {
            int row = m0 + ty * 8 + i;   // row = b*N_ + n
            int b = row >> 11;
            int n = row & (N_ - 1);
#pragma unroll
            for (int j = 0; j < 8; j++) {
                int col = n0 + tx * 8 + j;          // col = three*768 + h*64 + d
                float v = acc[i][j] + bias[col];
                int three = col / C_;
                int rem = col - three * C_;
                int h = rem >> 6;
                int d = rem & 63;
                int idx = (((b * H_ + h) * N_) + n) * D_ + d;
                if (three == 0)      g_Q[idx] = v * 0.125f;   // D^-0.5 pre-applied
                else if (three == 1) g_K[idx] = v;
                else                 g_V[idx] = v;
            }
        }
    }
}

// ---------------------------------------------------------------------------
// Flash attention: block = (64 q-rows) x one (b,h). 256 threads, 4x4 microtile.
// Online softmax with alibi bias + key padding mask. Output to g_ctx [B*N, C].
// ---------------------------------------------------------------------------
#define LDT 68   // padded SMEM row stride (floats)

__global__ __launch_bounds__(256) void flash_attn(
    const float* __restrict__ alibi, const int* __restrict__ mask)
{
    extern __shared__ float sm[];
    float* Qs = sm;                  // [64 d][LDT]  (d-major, transposed)
    float* Ks = Qs + 64 * LDT;       // [64 d][LDT]  (d-major, transposed)
    float* Vs = Ks + 64 * LDT;       // [64 c][LDT]  (key-major, natural)
    float* Ps = Vs + 64 * LDT;       // [64 c][LDT]  (key-major, transposed P)

    const int tid = threadIdx.x;
    const int tx = tid & 15;
    const int ty = tid >> 4;
    const int q0 = blockIdx.x * 64;
    const int h  = blockIdx.y;
    const int b  = blockIdx.z;
    const int bh = b * H_ + h;

    // Load Q tile (transposed to d-major)
    const float* Qg = g_Q + ((size_t)bh * N_ + q0) * D_;
    for (int idx = tid; idx < 64 * 16; idx += 256) {
        int r = idx >> 4;
        int d4 = (idx & 15) << 2;
        float4 v = *(const float4*)(Qg + r * D_ + d4);
        Qs[(d4 + 0) * LDT + r] = v.x;
        Qs[(d4 + 1) * LDT + r] = v.y;
        Qs[(d4 + 2) * LDT + r] = v.z;
        Qs[(d4 + 3) * LDT + r] = v.w;
    }

    float m_i[4], l_i[4], O[4][4];
#pragma unroll
    for (int i = 0; i < 4; i++) {
        m_i[i] = -1e30f;
        l_i[i] = 0.f;
#pragma unroll
        for (int j = 0; j < 4; j++) O[i][j] = 0.f;
    }

    const int* Mb = mask + b * N_;   // padding_mask as int32 (harness dtype)

    for (int k0 = 0; k0 < N_; k0 += 64) {
        __syncthreads();   // protect Ks/Vs/Ps reuse across iterations (and Qs init)

        const float* Kg = g_K + ((size_t)bh * N_ + k0) * D_;
        const float* Vg = g_V + ((size_t)bh * N_ + k0) * D_;
        for (int idx = tid; idx < 64 * 16; idx += 256) {
            int c = idx >> 4;
            int d4 = (idx & 15) << 2;
            float4 kv = *(const float4*)(Kg + c * D_ + d4);
            Ks[(d4 + 0) * LDT + c] = kv.x;
            Ks[(d4 + 1) * LDT + c] = kv.y;
            Ks[(d4 + 2) * LDT + c] = kv.z;
            Ks[(d4 + 3) * LDT + c] = kv.w;
            float4 vv = *(const float4*)(Vg + c * D_ + d4);
            *(float4*)&Vs[c * LDT + d4] = vv;
        }
        __syncthreads();

        // S = (Q*scale) @ K^T  for this 64x64 tile
        float S[4][4];
#pragma unroll
        for (int i = 0; i < 4; i++)
#pragma unroll
            for (int j = 0; j < 4; j++) S[i][j] = 0.f;

#pragma unroll 8
        for (int kk = 0; kk < 64; kk++) {
            float qa[4], kb[4];
            *(float4*)qa = *(const float4*)&Qs[kk * LDT + ty * 4];
            *(float4*)kb = *(const float4*)&Ks[kk * LDT + tx * 4];
#pragma unroll
            for (int i = 0; i < 4; i++)
#pragma unroll
                for (int j = 0; j < 4; j++)
                    S[i][j] += qa[i] * kb[j];
        }

        // + alibi, apply key padding mask (int32 flags)
        const float* Ab = alibi + ((size_t)bh * N_ + q0) * N_ + k0 + tx * 4;
#pragma unroll
        for (int i = 0; i < 4; i++) {
            float4 al = *(const float4*)(Ab + (size_t)(ty * 4 + i) * N_);
            S[i][0] += al.x; S[i][1] += al.y; S[i][2] += al.z; S[i][3] += al.w;
        }
        int4 mk = *(const int4*)(Mb + k0 + tx * 4);
        int mcol[4] = {mk.x, mk.y, mk.z, mk.w};
#pragma unroll
        for (int j = 0; j < 4; j++)
            if (mcol[j]) {
#pragma unroll
                for (int i = 0; i < 4; i++) S[i][j] = -1e30f;
            }

        // Online softmax (row groups = 16 lanes sharing ty)
#pragma unroll
        for (int i = 0; i < 4; i++) {
            float mx = fmaxf(fmaxf(S[i][0], S[i][1]), fmaxf(S[i][2], S[i][3]));
#pragma unroll
            for (int off = 8; off > 0; off >>= 1)
                mx = fmaxf(mx, __shfl_xor_sync(0xffffffffu, mx, off));
            float mnew = fmaxf(m_i[i], mx);
            float corr = __expf(m_i[i] - mnew);
            m_i[i] = mnew;
            float rs = 0.f;
#pragma unroll
            for (int j = 0; j < 4; j++) {
                float p = __expf(S[i][j] - mnew);
                S[i][j] = p;
                rs += p;
            }
#pragma unroll
            for (int off = 8; off > 0; off >>= 1)
                rs += __shfl_xor_sync(0xffffffffu, rs, off);
            l_i[i] = l_i[i] * corr + rs;
#pragma unroll
            for (int j = 0; j < 4; j++) O[i][j] *= corr;
        }

        // Stage P (transposed to key-major) for the PV GEMM
#pragma unroll
        for (int j = 0; j < 4; j++) {
            float4 pv;
            pv.x = S[0][j]; pv.y = S[1][j]; pv.z = S[2][j]; pv.w = S[3][j];
            *(float4*)&Ps[(tx * 4 + j) * LDT + ty * 4] = pv;
        }
        __syncthreads();

        // O += P @ V
#pragma unroll 8
        for (int c = 0; c < 64; c++) {
            float pa[4], vb[4];
            *(float4*)pa = *(const float4*)&Ps[c * LDT + ty * 4];
            *(float4*)vb = *(const float4*)&Vs[c * LDT + tx * 4];
#pragma unroll
            for (int i = 0; i < 4; i++)
#pragma unroll
                for (int j = 0; j < 4; j++)
                    O[i][j] += pa[i] * vb[j];
        }
    }

    // Normalize and write context in [B*N, C] layout (col = h*64 + d)
#pragma unroll
    for (int i = 0; i < 4; i++) {
        float inv = 1.f / l_i[i];
        float4 v;
        v.x = O[i][0] * inv; v.y = O[i][1] * inv;
        v.z = O[i][2] * inv; v.w = O[i][3] * inv;
        int row = b * N_ + q0 + ty * 4 + i;
        *(float4*)(g_ctx + (size_t)row * C_ + h * D_ + tx * 4) = v;
    }
}

// ---------------------------------------------------------------------------
extern "C" void kernel_launch(void* const* d_in, const int* in_sizes, int n_in,
                              void* d_out, int out_size)
{
    const float* x      = (const float*)d_in[0];
    const int*   mask   = (const int*)d_in[1];    // jnp.bool_ -> int32 in harness
    const float* alibi  = (const float*)d_in[2];
    const float* qkv_w  = (const float*)d_in[3];
    const float* qkv_b  = (const float*)d_in[4];
    const float* proj_w = (const float*)d_in[5];
    const float* proj_b = (const float*)d_in[6];
    float* out = (float*)d_out;

    void* ctx_ptr = nullptr;
    cudaGetSymbolAddress(&ctx_ptr, g_ctx);

    // 1) QKV projection + scatter to [B,H,N,D] (Q pre-scaled)
    sgemm128<1><<<dim3((3 * C_) / 128, M_ / 128), 256>>>(
        x, qkv_w, qkv_b, nullptr, C_, 3 * C_);

    // 2) Flash attention
    const int smem_bytes = 4 * 64 * LDT * 4;   // 69632 B
    cudaFuncSetAttribute(flash_attn, cudaFuncAttributeMaxDynamicSharedMemorySize,
                         smem_bytes);
    flash_attn<<<dim3(N_ / 64, H_, B_), 256, smem_bytes>>>(alibi, mask);

    // 3) Output projection
    sgemm128<0><<<dim3(C_ / 128, M_ / 128), 256>>>(
        (const float*)ctx_ptr, proj_w, proj_b, out, C_, C_);
}

// round 3
// speedup vs baseline: 1.9113x; 1.9113x over previous
#include <cuda_runtime.h>

#define H_ 12
#define C_ 768
#define D_ 64
#define B_ 4
#define N_ 2048
#define M_ 8192   // B_*N_

// Scratch (allocation-free: __device__ globals)
__device__ float g_Q[B_ * H_ * N_ * D_];
__device__ float g_K[B_ * H_ * N_ * D_];
__device__ float g_V[B_ * H_ * N_ * D_];
__device__ float g_ctx[M_ * C_];

// ---------------------------------------------------------------------------
// helpers
// ---------------------------------------------------------------------------
__device__ __forceinline__ void mma8(float* c, const unsigned* a, const unsigned* b) {
    asm volatile(
        "mma.sync.aligned.m16n8k8.row.col.f32.tf32.tf32.f32 "
        "{%0,%1,%2,%3},{%4,%5,%6,%7},{%8,%9},{%0,%1,%2,%3};"
        : "+f"(c[0]), "+f"(c[1]), "+f"(c[2]), "+f"(c[3])
        : "r"(a[0]), "r"(a[1]), "r"(a[2]), "r"(a[3]), "r"(b[0]), "r"(b[1]));
}

__device__ __forceinline__ float tf32_rna(float v) {
    unsigned u;
    asm("cvt.rna.tf32.f32 %0, %1;" : "=r"(u) : "f"(v));
    return __uint_as_float(u);
}
__device__ __forceinline__ unsigned tf32_rna_u(float v) {
    unsigned u;
    asm("cvt.rna.tf32.f32 %0, %1;" : "=r"(u) : "f"(v));
    return u;
}
__device__ __forceinline__ float tf32_hi(float v) {
    return __uint_as_float(__float_as_uint(v) & 0xFFFFE000u);
}

// ---------------------------------------------------------------------------
// 128x128 tf32 GEMM with 3xTF32 split (fp32-accurate). 256 threads, 8 warps.
// Warp tile 64x32 (4 m16 x 4 n8). K-step 8.
// MODE 0: Cout = acc + bias (proj, fp32 out)
// MODE 1: scatter into g_Q (x0.125) / g_K / g_V, values RNA-rounded to tf32
// ---------------------------------------------------------------------------
template <int MODE>
__global__ __launch_bounds__(256) void mm3x(
    const float* __restrict__ A, const float* __restrict__ Bm,
    const float* __restrict__ bias, float* __restrict__ Cout,
    int K, int N)
{
    __shared__ float Ah[8][136], Al[8][136], Bh[8][136], Bl[8][136];
    const int tid  = threadIdx.x;
    const int lane = tid & 31, warp = tid >> 5;
    const int g    = lane >> 2, tig = lane & 3;
    const int wm   = (warp >> 2) * 64, wn = (warp & 3) * 32;
    const int m0   = blockIdx.y * 128, n0 = blockIdx.x * 128;

    float acc[16][4];
#pragma unroll
    for (int t = 0; t < 16; t++)
#pragma unroll
        for (int r = 0; r < 4; r++) acc[t][r] = 0.f;

    const int aRow = tid >> 1, aC = (tid & 1) * 4;
    const int bRow = tid >> 5, bC = (tid & 31) * 4;
    const float* Ap = A + (size_t)(m0 + aRow) * K + aC;
    const float* Bp = Bm + (size_t)bRow * N + n0 + bC;

    for (int k0 = 0; k0 < K; k0 += 8) {
        float4 av = *(const float4*)(Ap + k0);
        float4 bv = *(const float4*)(Bp + (size_t)k0 * N);
        __syncthreads();
        {
            float h0 = tf32_hi(av.x); Ah[aC + 0][aRow] = h0; Al[aC + 0][aRow] = av.x - h0;
            float h1 = tf32_hi(av.y); Ah[aC + 1][aRow] = h1; Al[aC + 1][aRow] = av.y - h1;
            float h2 = tf32_hi(av.z); Ah[aC + 2][aRow] = h2; Al[aC + 2][aRow] = av.z - h2;
            float h3 = tf32_hi(av.w); Ah[aC + 3][aRow] = h3; Al[aC + 3][aRow] = av.w - h3;
            float4 bh, bl;
            bh.x = tf32_hi(bv.x); bl.x = bv.x - bh.x;
            bh.y = tf32_hi(bv.y); bl.y = bv.y - bh.y;
            bh.z = tf32_hi(bv.z); bl.z = bv.z - bh.z;
            bh.w = tf32_hi(bv.w); bl.w = bv.w - bh.w;
            *(float4*)&Bh[bRow][bC] = bh;
            *(float4*)&Bl[bRow][bC] = bl;
        }
        __syncthreads();

        unsigned af[4][4], xf[4][4], bf[4][2];
#pragma unroll
        for (int i = 0; i < 4; i++) {
            int m = wm + 16 * i + g;
            af[i][0] = *(const unsigned*)&Ah[tig][m];
            af[i][1] = *(const unsigned*)&Ah[tig][m + 8];
            af[i][2] = *(const unsigned*)&Ah[tig + 4][m];
            af[i][3] = *(const unsigned*)&Ah[tig + 4][m + 8];
        }
#pragma unroll
        for (int j = 0; j < 4; j++) {
            int n = wn + 8 * j + g;
            bf[j][0] = *(const unsigned*)&Bh[tig][n];
            bf[j][1] = *(const unsigned*)&Bh[tig + 4][n];
        }
#pragma unroll
        for (int i = 0; i < 4; i++)
#pragma unroll
            for (int j = 0; j < 4; j++) mma8(acc[i * 4 + j], af[i], bf[j]);

#pragma unroll
        for (int i = 0; i < 4; i++) {
            int m = wm + 16 * i + g;
            xf[i][0] = *(const unsigned*)&Al[tig][m];
            xf[i][1] = *(const unsigned*)&Al[tig][m + 8];
            xf[i][2] = *(const unsigned*)&Al[tig + 4][m];
            xf[i][3] = *(const unsigned*)&Al[tig + 4][m + 8];
        }
#pragma unroll
        for (int i = 0; i < 4; i++)
#pragma unroll
            for (int j = 0; j < 4; j++) mma8(acc[i * 4 + j], xf[i], bf[j]);

#pragma unroll
        for (int j = 0; j < 4; j++) {
            int n = wn + 8 * j + g;
            bf[j][0] = *(const unsigned*)&Bl[tig][n];
            bf[j][1] = *(const unsigned*)&Bl[tig + 4][n];
        }
#pragma unroll
        for (int i = 0; i < 4; i++)
#pragma unroll
            for (int j = 0; j < 4; j++) mma8(acc[i * 4 + j], af[i], bf[j]);
    }

    // epilogue
#pragma unroll
    for (int i = 0; i < 4; i++) {
#pragma unroll
        for (int j = 0; j < 4; j++) {
            int r0 = m0 + wm + 16 * i + g;
            int c0 = n0 + wn + 8 * j + 2 * tig;
            float b0 = bias[c0], b1 = bias[c0 + 1];
            if (MODE == 0) {
                float2 v0 = make_float2(acc[i * 4 + j][0] + b0, acc[i * 4 + j][1] + b1);
                float2 v1 = make_float2(acc[i * 4 + j][2] + b0, acc[i * 4 + j][3] + b1);
                *(float2*)(Cout + (size_t)r0 * N + c0) = v0;
                *(float2*)(Cout + (size_t)(r0 + 8) * N + c0) = v1;
            } else {
#pragma unroll
                for (int e = 0; e < 4; e++) {
                    int row = r0 + (e >> 1) * 8;
                    int col = c0 + (e & 1);
                    float v = acc[i * 4 + j][e] + ((e & 1) ? b1 : b0);
                    int three = col / C_;
                    int rem = col - three * C_;
                    int hh = rem >> 6, dd = rem & 63;
                    int bb = row >> 11, nn = row & (N_ - 1);
                    size_t idx = (((size_t)(bb * H_ + hh) * N_) + nn) * D_ + dd;
                    if (three == 0)      g_Q[idx] = tf32_rna(v * 0.125f);
                    else if (three == 1) g_K[idx] = tf32_rna(v);
                    else                 g_V[idx] = tf32_rna(v);
                }
            }
        }
    }
}

// ---------------------------------------------------------------------------
// Flash attention, tf32 mma. Block = 64 queries x (b,h), 128 threads (4 warps).
// Warp w owns q rows [16w,16w+16). Key tiles of 64. Online softmax in frags.
// Q/K/V are pre-rounded to tf32 (RNA) by the QKV epilogue -> in-loop
// truncation is exact; P gets cvt.rna.
// ---------------------------------------------------------------------------
#define ST_ 72   // smem row stride (floats), conflict-free for frag access

__global__ __launch_bounds__(128) void flash_tf32(
    const float* __restrict__ alibi, const int* __restrict__ mask)
{
    extern __shared__ float sm[];
    float* Ks  = sm;                   // [64][ST_]
    float* Vs  = sm + 64 * ST_;        // [64][ST_]
    float* PsA = sm + 2 * 64 * ST_;    // 4 x [16][ST_] (Q staging at start)
    float* Mf  = sm + 3 * 64 * ST_;    // [2048] mask addend

    const int tid  = threadIdx.x;
    const int lane = tid & 31, w = tid >> 5;
    const int g    = lane >> 2, tig = lane & 3;
    const int q0   = blockIdx.x * 64, h = blockIdx.y, b = blockIdx.z;
    const int bh   = b * H_ + h;
    float* Ps = PsA + w * 16 * ST_;

    // stage Q [64][64] into PsA region
    const float* Qg = g_Q + ((size_t)bh * N_ + q0) * D_;
    for (int idx = tid; idx < 64 * 16; idx += 128) {
        int r = idx >> 4, c4 = (idx & 15) << 2;
        *(float4*)&PsA[r * ST_ + c4] = *(const float4*)(Qg + r * D_ + c4);
    }
    // stage mask as additive bias
    const int* Mb = mask + b * N_;
    for (int kk = tid; kk < N_; kk += 128)
        Mf[kk] = Mb[kk] ? -1e30f : 0.f;
    __syncthreads();

    // Q frags (resident)
    unsigned qf[8][4];
    {
        int rlo = w * 16 + g;
#pragma unroll
        for (int kf = 0; kf < 8; kf++) {
            qf[kf][0] = *(const unsigned*)&PsA[rlo * ST_ + 8 * kf + tig];
            qf[kf][1] = *(const unsigned*)&PsA[(rlo + 8) * ST_ + 8 * kf + tig];
            qf[kf][2] = *(const unsigned*)&PsA[rlo * ST_ + 8 * kf + tig + 4];
            qf[kf][3] = *(const unsigned*)&PsA[(rlo + 8) * ST_ + 8 * kf + tig + 4];
        }
    }

    float Oa[8][4];
#pragma unroll
    for (int nt = 0; nt < 8; nt++)
#pragma unroll
        for (int r = 0; r < 4; r++) Oa[nt][r] = 0.f;
    float mlo = -1e30f, mhi = -1e30f, llo = 0.f, lhi = 0.f;

    const float* Alo = alibi + ((size_t)bh * N_ + q0 + w * 16 + g) * N_;
    const float* Ahi = Alo + 8 * (size_t)N_;

    for (int kt = 0; kt < N_ / 64; kt++) {
        __syncthreads();   // prior reads of Ks/Vs (and Q-frag builds) complete
        const float* Kt = g_K + ((size_t)bh * N_ + kt * 64) * D_;
        const float* Vt = g_V + ((size_t)bh * N_ + kt * 64) * D_;
        for (int idx = tid; idx < 64 * 16; idx += 128) {
            int r = idx >> 4, c4 = (idx & 15) << 2;
            *(float4*)&Ks[r * ST_ + c4] = *(const float4*)(Kt + r * D_ + c4);
            *(float4*)&Vs[r * ST_ + c4] = *(const float4*)(Vt + r * D_ + c4);
        }
        __syncthreads();

        // S = Q K^T (tile 16x64 per warp)
        float Sa[8][4];
#pragma unroll
        for (int nt = 0; nt < 8; nt++)
#pragma unroll
            for (int r = 0; r < 4; r++) Sa[nt][r] = 0.f;
#pragma unroll
        for (int nt = 0; nt < 8; nt++) {
            const float* kr = &Ks[(8 * nt + g) * ST_];
#pragma unroll
            for (int kf = 0; kf < 8; kf++) {
                unsigned bfr[2];
                bfr[0] = *(const unsigned*)&kr[8 * kf + tig];
                bfr[1] = *(const unsigned*)&kr[8 * kf + tig + 4];
                mma8(Sa[nt], qf[kf], bfr);
            }
        }

        // + alibi + mask
        int kbase = kt * 64;
#pragma unroll
        for (int nt = 0; nt < 8; nt++) {
            int c = kbase + 8 * nt + 2 * tig;
            float2 alo = *(const float2*)(Alo + c);
            float2 ahi = *(const float2*)(Ahi + c);
            float m0v = Mf[c], m1v = Mf[c + 1];
            Sa[nt][0] += alo.x + m0v;
            Sa[nt][1] += alo.y + m1v;
            Sa[nt][2] += ahi.x + m0v;
            Sa[nt][3] += ahi.y + m1v;
        }

        // online softmax: rows (w*16+g) [c0,c1] and (+8) [c2,c3]
        float mx0 = -1e38f, mx1 = -1e38f;
#pragma unroll
        for (int nt = 0; nt < 8; nt++) {
            mx0 = fmaxf(mx0, fmaxf(Sa[nt][0], Sa[nt][1]));
            mx1 = fmaxf(mx1, fmaxf(Sa[nt][2], Sa[nt][3]));
        }
        mx0 = fmaxf(mx0, __shfl_xor_sync(0xffffffffu, mx0, 1));
        mx0 = fmaxf(mx0, __shfl_xor_sync(0xffffffffu, mx0, 2));
        mx1 = fmaxf(mx1, __shfl_xor_sync(0xffffffffu, mx1, 1));
        mx1 = fmaxf(mx1, __shfl_xor_sync(0xffffffffu, mx1, 2));
        float mn0 = fmaxf(mlo, mx0), mn1 = fmaxf(mhi, mx1);
        float cr0 = __expf(mlo - mn0), cr1 = __expf(mhi - mn1);
        mlo = mn0; mhi = mn1;
        float rs0 = 0.f, rs1 = 0.f;
#pragma unroll
        for (int nt = 0; nt < 8; nt++) {
            float p0 = __expf(Sa[nt][0] - mn0);
            float p1 = __expf(Sa[nt][1] - mn0);
            float p2 = __expf(Sa[nt][2] - mn1);
            float p3 = __expf(Sa[nt][3] - mn1);
            Sa[nt][0] = p0; Sa[nt][1] = p1; Sa[nt][2] = p2; Sa[nt][3] = p3;
            rs0 += p0 + p1;
            rs1 += p2 + p3;
        }
        rs0 += __shfl_xor_sync(0xffffffffu, rs0, 1);
        rs0 += __shfl_xor_sync(0xffffffffu, rs0, 2);
        rs1 += __shfl_xor_sync(0xffffffffu, rs1, 1);
        rs1 += __shfl_xor_sync(0xffffffffu, rs1, 2);
        llo = llo * cr0 + rs0;
        lhi = lhi * cr1 + rs1;
#pragma unroll
        for (int nt = 0; nt < 8; nt++) {
            Oa[nt][0] *= cr0; Oa[nt][1] *= cr0;
            Oa[nt][2] *= cr1; Oa[nt][3] *= cr1;
        }

        // stage P (warp-private) and run PV
#pragma unroll
        for (int nt = 0; nt < 8; nt++) {
            *(float2*)&Ps[g * ST_ + 8 * nt + 2 * tig] = make_float2(Sa[nt][0], Sa[nt][1]);
            *(float2*)&Ps[(g + 8) * ST_ + 8 * nt + 2 * tig] = make_float2(Sa[nt][2], Sa[nt][3]);
        }
        __syncwarp();

        unsigned pf[8][4];
#pragma unroll
        for (int kf = 0; kf < 8; kf++) {
            pf[kf][0] = tf32_rna_u(Ps[g * ST_ + 8 * kf + tig]);
            pf[kf][1] = tf32_rna_u(Ps[(g + 8) * ST_ + 8 * kf + tig]);
            pf[kf][2] = tf32_rna_u(Ps[g * ST_ + 8 * kf + tig + 4]);
            pf[kf][3] = tf32_rna_u(Ps[(g + 8) * ST_ + 8 * kf + tig + 4]);
        }
#pragma unroll
        for (int nt = 0; nt < 8; nt++) {
#pragma unroll
            for (int kf = 0; kf < 8; kf++) {
                unsigned vb[2];
                vb[0] = *(const unsigned*)&Vs[(8 * kf + tig) * ST_ + 8 * nt + g];
                vb[1] = *(const unsigned*)&Vs[(8 * kf + tig + 4) * ST_ + 8 * nt + g];
                mma8(Oa[nt], pf[kf], vb);
            }
        }
    }

    // normalize + write ctx [B*N, C], col = h*64 + d
    float i0 = 1.f / llo, i1 = 1.f / lhi;
    float* Cr  = g_ctx + (size_t)(b * N_ + q0 + w * 16 + g) * C_ + h * D_;
    float* Cr2 = Cr + 8 * (size_t)C_;
#pragma unroll
    for (int nt = 0; nt < 8; nt++) {
        int c = 8 * nt + 2 * tig;
        *(float2*)(Cr + c)  = make_float2(Oa[nt][0] * i0, Oa[nt][1] * i0);
        *(float2*)(Cr2 + c) = make_float2(Oa[nt][2] * i1, Oa[nt][3] * i1);
    }
}

// ---------------------------------------------------------------------------
extern "C" void kernel_launch(void* const* d_in, const int* in_sizes, int n_in,
                              void* d_out, int out_size)
{
    const float* x      = (const float*)d_in[0];
    const int*   mask   = (const int*)d_in[1];
    const float* alibi  = (const float*)d_in[2];
    const float* qkv_w  = (const float*)d_in[3];
    const float* qkv_b  = (const float*)d_in[4];
    const float* proj_w = (const float*)d_in[5];
    const float* proj_b = (const float*)d_in[6];
    float* out = (float*)d_out;

    void* ctx_ptr = nullptr;
    cudaGetSymbolAddress(&ctx_ptr, g_ctx);

    // 1) QKV projection (3xTF32) -> scatter tf32-rounded Q/K/V
    mm3x<1><<<dim3((3 * C_) / 128, M_ / 128), 256>>>(
        x, qkv_w, qkv_b, nullptr, C_, 3 * C_);

    // 2) Flash attention (tf32 mma)
    const int smem_bytes = (3 * 64 * ST_ + N_) * 4;   // 63488 B
    cudaFuncSetAttribute(flash_tf32, cudaFuncAttributeMaxDynamicSharedMemorySize,
                         smem_bytes);
    flash_tf32<<<dim3(N_ / 64, H_, B_), 128, smem_bytes>>>(alibi, mask);

    // 3) Output projection (3xTF32)
    mm3x<0><<<dim3(C_ / 128, M_ / 128), 256>>>(
        (const float*)ctx_ptr, proj_w, proj_b, out, C_, C_);
}

// round 4
// speedup vs baseline: 2.2161x; 1.1595x over previous
#include <cuda_runtime.h>

#define H_ 12
#define C_ 768
#define D_ 64
#define B_ 4
#define N_ 2048
#define M_ 8192   // B_*N_

// Scratch (allocation-free: __device__ globals)
__device__ float g_Q[B_ * H_ * N_ * D_];
__device__ float g_K[B_ * H_ * N_ * D_];
__device__ float g_V[B_ * H_ * N_ * D_];
__device__ float g_ctx[M_ * C_];

// ---------------------------------------------------------------------------
// helpers
// ---------------------------------------------------------------------------
__device__ __forceinline__ void mma8(float* c, const unsigned* a, const unsigned* b) {
    asm volatile(
        "mma.sync.aligned.m16n8k8.row.col.f32.tf32.tf32.f32 "
        "{%0,%1,%2,%3},{%4,%5,%6,%7},{%8,%9},{%0,%1,%2,%3};"
        : "+f"(c[0]), "+f"(c[1]), "+f"(c[2]), "+f"(c[3])
        : "r"(a[0]), "r"(a[1]), "r"(a[2]), "r"(a[3]), "r"(b[0]), "r"(b[1]));
}

__device__ __forceinline__ float tf32_rna(float v) {
    unsigned u;
    asm("cvt.rna.tf32.f32 %0, %1;" : "=r"(u) : "f"(v));
    return __uint_as_float(u);
}
__device__ __forceinline__ unsigned tf32_rna_u(float v) {
    unsigned u;
    asm("cvt.rna.tf32.f32 %0, %1;" : "=r"(u) : "f"(v));
    return u;
}
__device__ __forceinline__ float tf32_hi(float v) {
    return __uint_as_float(__float_as_uint(v) & 0xFFFFE000u);
}

// ---------------------------------------------------------------------------
// QKV: 128x128 tf32 GEMM, 1xTF32 (inputs RNA-rounded). 256 threads, 8 warps.
// Scatters into g_Q (x0.125) / g_K / g_V, values RNA-rounded to tf32.
// ---------------------------------------------------------------------------
__global__ __launch_bounds__(256) void mm1x_qkv(
    const float* __restrict__ A, const float* __restrict__ Bm,
    const float* __restrict__ bias, int K, int N)
{
    __shared__ float Ah[8][136], Bh[8][136];
    const int tid  = threadIdx.x;
    const int lane = tid & 31, warp = tid >> 5;
    const int g    = lane >> 2, tig = lane & 3;
    const int wm   = (warp >> 2) * 64, wn = (warp & 3) * 32;
    const int m0   = blockIdx.y * 128, n0 = blockIdx.x * 128;

    float acc[16][4];
#pragma unroll
    for (int t = 0; t < 16; t++)
#pragma unroll
        for (int r = 0; r < 4; r++) acc[t][r] = 0.f;

    const int aRow = tid >> 1, aC = (tid & 1) * 4;
    const int bRow = tid >> 5, bC = (tid & 31) * 4;
    const float* Ap = A + (size_t)(m0 + aRow) * K + aC;
    const float* Bp = Bm + (size_t)bRow * N + n0 + bC;

    for (int k0 = 0; k0 < K; k0 += 8) {
        float4 av = *(const float4*)(Ap + k0);
        float4 bv = *(const float4*)(Bp + (size_t)k0 * N);
        __syncthreads();
        Ah[aC + 0][aRow] = tf32_rna(av.x);
        Ah[aC + 1][aRow] = tf32_rna(av.y);
        Ah[aC + 2][aRow] = tf32_rna(av.z);
        Ah[aC + 3][aRow] = tf32_rna(av.w);
        float4 bh;
        bh.x = tf32_rna(bv.x); bh.y = tf32_rna(bv.y);
        bh.z = tf32_rna(bv.z); bh.w = tf32_rna(bv.w);
        *(float4*)&Bh[bRow][bC] = bh;
        __syncthreads();

        unsigned af[4][4], bf[4][2];
#pragma unroll
        for (int i = 0; i < 4; i++) {
            int m = wm + 16 * i + g;
            af[i][0] = *(const unsigned*)&Ah[tig][m];
            af[i][1] = *(const unsigned*)&Ah[tig][m + 8];
            af[i][2] = *(const unsigned*)&Ah[tig + 4][m];
            af[i][3] = *(const unsigned*)&Ah[tig + 4][m + 8];
        }
#pragma unroll
        for (int j = 0; j < 4; j++) {
            int n = wn + 8 * j + g;
            bf[j][0] = *(const unsigned*)&Bh[tig][n];
            bf[j][1] = *(const unsigned*)&Bh[tig + 4][n];
        }
#pragma unroll
        for (int i = 0; i < 4; i++)
#pragma unroll
            for (int j = 0; j < 4; j++) mma8(acc[i * 4 + j], af[i], bf[j]);
    }

    // epilogue: scatter Q/K/V (tf32-rounded)
#pragma unroll
    for (int i = 0; i < 4; i++) {
#pragma unroll
        for (int j = 0; j < 4; j++) {
            int r0 = m0 + wm + 16 * i + g;
            int c0 = n0 + wn + 8 * j + 2 * tig;
            float b0 = bias[c0], b1 = bias[c0 + 1];
#pragma unroll
            for (int e = 0; e < 4; e++) {
                int row = r0 + (e >> 1) * 8;
                int col = c0 + (e & 1);
                float v = acc[i * 4 + j][e] + ((e & 1) ? b1 : b0);
                int three = col / C_;
                int rem = col - three * C_;
                int hh = rem >> 6, dd = rem & 63;
                int bb = row >> 11, nn = row & (N_ - 1);
                size_t idx = (((size_t)(bb * H_ + hh) * N_) + nn) * D_ + dd;
                if (three == 0)      g_Q[idx] = tf32_rna(v * 0.125f);
                else if (three == 1) g_K[idx] = tf32_rna(v);
                else                 g_V[idx] = tf32_rna(v);
            }
        }
    }
}

// ---------------------------------------------------------------------------
// Proj: 128x128 tf32 GEMM with 3xTF32 split (fp32-accurate). 256 threads.
// Cout = acc + bias (fp32 out, final output -> keep full precision)
// ---------------------------------------------------------------------------
__global__ __launch_bounds__(256) void mm3x_proj(
    const float* __restrict__ A, const float* __restrict__ Bm,
    const float* __restrict__ bias, float* __restrict__ Cout,
    int K, int N)
{
    __shared__ float Ah[8][136], Al[8][136], Bh[8][136], Bl[8][136];
    const int tid  = threadIdx.x;
    const int lane = tid & 31, warp = tid >> 5;
    const int g    = lane >> 2, tig = lane & 3;
    const int wm   = (warp >> 2) * 64, wn = (warp & 3) * 32;
    const int m0   = blockIdx.y * 128, n0 = blockIdx.x * 128;

    float acc[16][4];
#pragma unroll
    for (int t = 0; t < 16; t++)
#pragma unroll
        for (int r = 0; r < 4; r++) acc[t][r] = 0.f;

    const int aRow = tid >> 1, aC = (tid & 1) * 4;
    const int bRow = tid >> 5, bC = (tid & 31) * 4;
    const float* Ap = A + (size_t)(m0 + aRow) * K + aC;
    const float* Bp = Bm + (size_t)bRow * N + n0 + bC;

    for (int k0 = 0; k0 < K; k0 += 8) {
        float4 av = *(const float4*)(Ap + k0);
        float4 bv = *(const float4*)(Bp + (size_t)k0 * N);
        __syncthreads();
        {
            float h0 = tf32_hi(av.x); Ah[aC + 0][aRow] = h0; Al[aC + 0][aRow] = av.x - h0;
            float h1 = tf32_hi(av.y); Ah[aC + 1][aRow] = h1; Al[aC + 1][aRow] = av.y - h1;
            float h2 = tf32_hi(av.z); Ah[aC + 2][aRow] = h2; Al[aC + 2][aRow] = av.z - h2;
            float h3 = tf32_hi(av.w); Ah[aC + 3][aRow] = h3; Al[aC + 3][aRow] = av.w - h3;
            float4 bh, bl;
            bh.x = tf32_hi(bv.x); bl.x = bv.x - bh.x;
            bh.y = tf32_hi(bv.y); bl.y = bv.y - bh.y;
            bh.z = tf32_hi(bv.z); bl.z = bv.z - bh.z;
            bh.w = tf32_hi(bv.w); bl.w = bv.w - bh.w;
            *(float4*)&Bh[bRow][bC] = bh;
            *(float4*)&Bl[bRow][bC] = bl;
        }
        __syncthreads();

        unsigned af[4][4], xf[4][4], bf[4][2];
#pragma unroll
        for (int i = 0; i < 4; i++) {
            int m = wm + 16 * i + g;
            af[i][0] = *(const unsigned*)&Ah[tig][m];
            af[i][1] = *(const unsigned*)&Ah[tig][m + 8];
            af[i][2] = *(const unsigned*)&Ah[tig + 4][m];
            af[i][3] = *(const unsigned*)&Ah[tig + 4][m + 8];
        }
#pragma unroll
        for (int j = 0; j < 4; j++) {
            int n = wn + 8 * j + g;
            bf[j][0] = *(const unsigned*)&Bh[tig][n];
            bf[j][1] = *(const unsigned*)&Bh[tig + 4][n];
        }
#pragma unroll
        for (int i = 0; i < 4; i++)
#pragma unroll
            for (int j = 0; j < 4; j++) mma8(acc[i * 4 + j], af[i], bf[j]);

#pragma unroll
        for (int i = 0; i < 4; i++) {
            int m = wm + 16 * i + g;
            xf[i][0] = *(const unsigned*)&Al[tig][m];
            xf[i][1] = *(const unsigned*)&Al[tig][m + 8];
            xf[i][2] = *(const unsigned*)&Al[tig + 4][m];
            xf[i][3] = *(const unsigned*)&Al[tig + 4][m + 8];
        }
#pragma unroll
        for (int i = 0; i < 4; i++)
#pragma unroll
            for (int j = 0; j < 4; j++) mma8(acc[i * 4 + j], xf[i], bf[j]);

#pragma unroll
        for (int j = 0; j < 4; j++) {
            int n = wn + 8 * j + g;
            bf[j][0] = *(const unsigned*)&Bl[tig][n];
            bf[j][1] = *(const unsigned*)&Bl[tig + 4][n];
        }
#pragma unroll
        for (int i = 0; i < 4; i++)
#pragma unroll
            for (int j = 0; j < 4; j++) mma8(acc[i * 4 + j], af[i], bf[j]);
    }

#pragma unroll
    for (int i = 0; i < 4; i++) {
#pragma unroll
        for (int j = 0; j < 4; j++) {
            int r0 = m0 + wm + 16 * i + g;
            int c0 = n0 + wn + 8 * j + 2 * tig;
            float b0 = bias[c0], b1 = bias[c0 + 1];
            float2 v0 = make_float2(acc[i * 4 + j][0] + b0, acc[i * 4 + j][1] + b1);
            float2 v1 = make_float2(acc[i * 4 + j][2] + b0, acc[i * 4 + j][3] + b1);
            *(float2*)(Cout + (size_t)r0 * N + c0) = v0;
            *(float2*)(Cout + (size_t)(r0 + 8) * N + c0) = v1;
        }
    }
}

// ---------------------------------------------------------------------------
// Flash attention, tf32 mma. Block = 64 queries x (b,h), 128 threads (4 warps).
// ST_=76 (== 12 mod 32): all fragment LDS patterns bank-conflict-free.
// Mask read directly from gmem (L2-resident), no smem staging.
// ---------------------------------------------------------------------------
#define ST_ 76

__global__ __launch_bounds__(128) void flash_tf32(
    const float* __restrict__ alibi, const int* __restrict__ mask)
{
    extern __shared__ float sm[];
    float* Ks  = sm;                   // [64][ST_]
    float* Vs  = sm + 64 * ST_;        // [64][ST_]
    float* PsA = sm + 2 * 64 * ST_;    // 4 x [16][ST_] (Q staging at start)

    const int tid  = threadIdx.x;
    const int lane = tid & 31, w = tid >> 5;
    const int g    = lane >> 2, tig = lane & 3;
    const int q0   = blockIdx.x * 64, h = blockIdx.y, b = blockIdx.z;
    const int bh   = b * H_ + h;
    float* Ps = PsA + w * 16 * ST_;

    // stage Q [64][64] into PsA region
    const float* Qg = g_Q + ((size_t)bh * N_ + q0) * D_;
    for (int idx = tid; idx < 64 * 16; idx += 128) {
        int r = idx >> 4, c4 = (idx & 15) << 2;
        *(float4*)&PsA[r * ST_ + c4] = *(const float4*)(Qg + r * D_ + c4);
    }
    __syncthreads();

    // Q frags (resident)
    unsigned qf[8][4];
    {
        int rlo = w * 16 + g;
#pragma unroll
        for (int kf = 0; kf < 8; kf++) {
            qf[kf][0] = *(const unsigned*)&PsA[rlo * ST_ + 8 * kf + tig];
            qf[kf][1] = *(const unsigned*)&PsA[(rlo + 8) * ST_ + 8 * kf + tig];
            qf[kf][2] = *(const unsigned*)&PsA[rlo * ST_ + 8 * kf + tig + 4];
            qf[kf][3] = *(const unsigned*)&PsA[(rlo + 8) * ST_ + 8 * kf + tig + 4];
        }
    }

    float Oa[8][4];
#pragma unroll
    for (int nt = 0; nt < 8; nt++)
#pragma unroll
        for (int r = 0; r < 4; r++) Oa[nt][r] = 0.f;
    float mlo = -1e30f, mhi = -1e30f, llo = 0.f, lhi = 0.f;

    const float* Alo = alibi + ((size_t)bh * N_ + q0 + w * 16 + g) * N_;
    const float* Ahi = Alo + 8 * (size_t)N_;
    const int* Mb = mask + b * N_;

    for (int kt = 0; kt < N_ / 64; kt++) {
        __syncthreads();   // prior reads of Ks/Vs (and Q-frag builds) complete
        const float* Kt = g_K + ((size_t)bh * N_ + kt * 64) * D_;
        const float* Vt = g_V + ((size_t)bh * N_ + kt * 64) * D_;
        for (int idx = tid; idx < 64 * 16; idx += 128) {
            int r = idx >> 4, c4 = (idx & 15) << 2;
            *(float4*)&Ks[r * ST_ + c4] = *(const float4*)(Kt + r * D_ + c4);
            *(float4*)&Vs[r * ST_ + c4] = *(const float4*)(Vt + r * D_ + c4);
        }
        __syncthreads();

        // S = Q K^T (tile 16x64 per warp)
        float Sa[8][4];
#pragma unroll
        for (int nt = 0; nt < 8; nt++)
#pragma unroll
            for (int r = 0; r < 4; r++) Sa[nt][r] = 0.f;
#pragma unroll
        for (int nt = 0; nt < 8; nt++) {
            const float* kr = &Ks[(8 * nt + g) * ST_];
#pragma unroll
            for (int kf = 0; kf < 8; kf++) {
                unsigned bfr[2];
                bfr[0] = *(const unsigned*)&kr[8 * kf + tig];
                bfr[1] = *(const unsigned*)&kr[8 * kf + tig + 4];
                mma8(Sa[nt], qf[kf], bfr);
            }
        }

        // + alibi + mask (mask via L2)
        int kbase = kt * 64;
#pragma unroll
        for (int nt = 0; nt < 8; nt++) {
            int c = kbase + 8 * nt + 2 * tig;
            float2 alo = *(const float2*)(Alo + c);
            float2 ahi = *(const float2*)(Ahi + c);
            int2 mk = *(const int2*)(Mb + c);
            float m0v = mk.x ? -1e30f : 0.f;
            float m1v = mk.y ? -1e30f : 0.f;
            Sa[nt][0] += alo.x + m0v;
            Sa[nt][1] += alo.y + m1v;
            Sa[nt][2] += ahi.x + m0v;
            Sa[nt][3] += ahi.y + m1v;
        }

        // online softmax: rows (w*16+g) [c0,c1] and (+8) [c2,c3]
        float mx0 = -1e38f, mx1 = -1e38f;
#pragma unroll
        for (int nt = 0; nt < 8; nt++) {
            mx0 = fmaxf(mx0, fmaxf(Sa[nt][0], Sa[nt][1]));
            mx1 = fmaxf(mx1, fmaxf(Sa[nt][2], Sa[nt][3]));
        }
        mx0 = fmaxf(mx0, __shfl_xor_sync(0xffffffffu, mx0, 1));
        mx0 = fmaxf(mx0, __shfl_xor_sync(0xffffffffu, mx0, 2));
        mx1 = fmaxf(mx1, __shfl_xor_sync(0xffffffffu, mx1, 1));
        mx1 = fmaxf(mx1, __shfl_xor_sync(0xffffffffu, mx1, 2));
        float mn0 = fmaxf(mlo, mx0), mn1 = fmaxf(mhi, mx1);
        float cr0 = __expf(mlo - mn0), cr1 = __expf(mhi - mn1);
        mlo = mn0; mhi = mn1;
        float rs0 = 0.f, rs1 = 0.f;
#pragma unroll
        for (int nt = 0; nt < 8; nt++) {
            float p0 = __expf(Sa[nt][0] - mn0);
            float p1 = __expf(Sa[nt][1] - mn0);
            float p2 = __expf(Sa[nt][2] - mn1);
            float p3 = __expf(Sa[nt][3] - mn1);
            Sa[nt][0] = p0; Sa[nt][1] = p1; Sa[nt][2] = p2; Sa[nt][3] = p3;
            rs0 += p0 + p1;
            rs1 += p2 + p3;
        }
        rs0 += __shfl_xor_sync(0xffffffffu, rs0, 1);
        rs0 += __shfl_xor_sync(0xffffffffu, rs0, 2);
        rs1 += __shfl_xor_sync(0xffffffffu, rs1, 1);
        rs1 += __shfl_xor_sync(0xffffffffu, rs1, 2);
        llo = llo * cr0 + rs0;
        lhi = lhi * cr1 + rs1;
#pragma unroll
        for (int nt = 0; nt < 8; nt++) {
            Oa[nt][0] *= cr0; Oa[nt][1] *= cr0;
            Oa[nt][2] *= cr1; Oa[nt][3] *= cr1;
        }

        // stage P (warp-private) and run PV
#pragma unroll
        for (int nt = 0; nt < 8; nt++) {
            *(float2*)&Ps[g * ST_ + 8 * nt + 2 * tig] = make_float2(Sa[nt][0], Sa[nt][1]);
            *(float2*)&Ps[(g + 8) * ST_ + 8 * nt + 2 * tig] = make_float2(Sa[nt][2], Sa[nt][3]);
        }
        __syncwarp();

        unsigned pf[8][4];
#pragma unroll
        for (int kf = 0; kf < 8; kf++) {
            pf[kf][0] = tf32_rna_u(Ps[g * ST_ + 8 * kf + tig]);
            pf[kf][1] = tf32_rna_u(Ps[(g + 8) * ST_ + 8 * kf + tig]);
            pf[kf][2] = tf32_rna_u(Ps[g * ST_ + 8 * kf + tig + 4]);
            pf[kf][3] = tf32_rna_u(Ps[(g + 8) * ST_ + 8 * kf + tig + 4]);
        }
#pragma unroll
        for (int nt = 0; nt < 8; nt++) {
#pragma unroll
            for (int kf = 0; kf < 8; kf++) {
                unsigned vb[2];
                vb[0] = *(const unsigned*)&Vs[(8 * kf + tig) * ST_ + 8 * nt + g];
                vb[1] = *(const unsigned*)&Vs[(8 * kf + tig + 4) * ST_ + 8 * nt + g];
                mma8(Oa[nt], pf[kf], vb);
            }
        }
    }

    // normalize + write ctx [B*N, C], col = h*64 + d
    float i0 = 1.f / llo, i1 = 1.f / lhi;
    float* Cr  = g_ctx + (size_t)(b * N_ + q0 + w * 16 + g) * C_ + h * D_;
    float* Cr2 = Cr + 8 * (size_t)C_;
#pragma unroll
    for (int nt = 0; nt < 8; nt++) {
        int c = 8 * nt + 2 * tig;
        *(float2*)(Cr + c)  = make_float2(Oa[nt][0] * i0, Oa[nt][1] * i0);
        *(float2*)(Cr2 + c) = make_float2(Oa[nt][2] * i1, Oa[nt][3] * i1);
    }
}

// ---------------------------------------------------------------------------
extern "C" void kernel_launch(void* const* d_in, const int* in_sizes, int n_in,
                              void* d_out, int out_size)
{
    const float* x      = (const float*)d_in[0];
    const int*   mask   = (const int*)d_in[1];
    const float* alibi  = (const float*)d_in[2];
    const float* qkv_w  = (const float*)d_in[3];
    const float* qkv_b  = (const float*)d_in[4];
    const float* proj_w = (const float*)d_in[5];
    const float* proj_b = (const float*)d_in[6];
    float* out = (float*)d_out;

    void* ctx_ptr = nullptr;
    cudaGetSymbolAddress(&ctx_ptr, g_ctx);

    // 1) QKV projection (1xTF32) -> scatter tf32-rounded Q/K/V
    mm1x_qkv<<<dim3((3 * C_) / 128, M_ / 128), 256>>>(
        x, qkv_w, qkv_b, C_, 3 * C_);

    // 2) Flash attention (tf32 mma)
    const int smem_bytes = 3 * 64 * ST_ * 4;   // 58368 B
    cudaFuncSetAttribute(flash_tf32, cudaFuncAttributeMaxDynamicSharedMemorySize,
                         smem_bytes);
    flash_tf32<<<dim3(N_ / 64, H_, B_), 128, smem_bytes>>>(alibi, mask);

    // 3) Output projection (3xTF32, full precision on final output)
    mm3x_proj<<<dim3(C_ / 128, M_ / 128), 256>>>(
        (const float*)ctx_ptr, proj_w, proj_b, out, C_, C_);
}